// round 9
// baseline (speedup 1.0000x reference)
#include <cuda_runtime.h>
#include <math.h>
#include <stdint.h>

// ---------------------------------------------------------------------------
// Problem constants
// ---------------------------------------------------------------------------
#define BN 2
#define TN 1024
#define CN 768
#define HN 12
#define HDN 64
#define LN 4
#define DIN 64
#define VN 50304
#define CFN 3072          // 4*C
#define MN (BN*TN)        // 2048 rows

// ---------------------------------------------------------------------------
// Scratch (static device globals; allocation APIs are forbidden)
// ---------------------------------------------------------------------------
__device__ float g_x[MN*CN];
__device__ float g_h[MN*CN];
__device__ float g_qkv[MN*3*CN];
__device__ float g_y[MN*CN];
__device__ float g_qk[MN*128];      // fused [qint(64) | kint(64)] activations
__device__ float g_w2[128*CN];      // concatenated qint_w/kint_w
__device__ float g_p[BN*TN*TN];     // rawT then log-p, layout [b][k][q]
__device__ float g_mask[BN*TN*TN];  // accumulated attn_mask, layout [b][q][k]
__device__ float g_fc[MN*CFN];

// ---------------------------------------------------------------------------
// Embedding: x = wte[idx] + wpe[:T]
// ---------------------------------------------------------------------------
__global__ void k_embed(const float* __restrict__ wte, const float* __restrict__ wpe,
                        const int* __restrict__ idx, float* __restrict__ x) {
    int i = blockIdx.x * blockDim.x + threadIdx.x;
    if (i >= MN*CN) return;
    int c = i % CN;
    int bt = i / CN;
    int t = bt % TN;
    x[i] = wte[(size_t)idx[bt]*CN + c] + wpe[t*CN + c];
}

__global__ void k_zero(float* __restrict__ p, int n) {
    int i = blockIdx.x * blockDim.x + threadIdx.x;
    for (; i < n; i += gridDim.x * blockDim.x) p[i] = 0.0f;
}

// concat qint_w / kint_w into one [128, CN] weight
__global__ void k_catw(const float* __restrict__ qw, const float* __restrict__ kw,
                       float* __restrict__ dst) {
    int i = blockIdx.x * blockDim.x + threadIdx.x;
    if (i >= 128*CN) return;
    int row = i / CN, c = i % CN;
    dst[i] = (row < 64) ? qw[row*CN + c] : kw[(row-64)*CN + c];
}

// ---------------------------------------------------------------------------
// LayerNorm (block per row, C = 768 = 3*256)
// ---------------------------------------------------------------------------
__global__ void k_ln(const float* __restrict__ x, const float* __restrict__ w,
                     const float* __restrict__ b, float* __restrict__ o) {
    int row = blockIdx.x;
    const float* xr = x + (size_t)row*CN;
    float* orow = o + (size_t)row*CN;
    __shared__ float red[256];
    int t = threadIdx.x;
    float lx0 = xr[t], lx1 = xr[t+256], lx2 = xr[t+512];
    red[t] = lx0 + lx1 + lx2;
    __syncthreads();
    for (int st = 128; st > 0; st >>= 1) {
        if (t < st) red[t] += red[t+st];
        __syncthreads();
    }
    float mu = red[0] / (float)CN;
    __syncthreads();
    float d0 = lx0-mu, d1 = lx1-mu, d2 = lx2-mu;
    red[t] = d0*d0 + d1*d1 + d2*d2;
    __syncthreads();
    for (int st = 128; st > 0; st >>= 1) {
        if (t < st) red[t] += red[t+st];
        __syncthreads();
    }
    float var = red[0] / (float)CN;
    float inv = 1.0f / sqrtf(var + 1e-5f);
    orow[t]     = d0*inv*w[t]     + b[t];
    orow[t+256] = d1*inv*w[t+256] + b[t+256];
    orow[t+512] = d2*inv*w[t+512] + b[t+512];
}

// ---------------------------------------------------------------------------
// GELU helper (tanh approximation, matching reference constants)
// ---------------------------------------------------------------------------
__device__ __forceinline__ float gelu1(float v) {
    float inner = 0.7978845608028654f * (v + 0.044715f*v*v*v);
    return 0.5f*v*(1.0f + tanhf(inner));
}

// ---------------------------------------------------------------------------
// 2xBF16 tensor-core GEMM (hi/lo split, hh+hl+lh), double-buffered smem,
// ldmatrix fragment loads. Block tile 128x128, 8 warps (4Mx2N), warp 32x64.
// O[m,n] = sum_k A[m,k]*W[n,k] (+bias[n]) (+res[m,n]) (optional gelu)
// A:[M,K] row stride lda, W:[N,K] row stride ldb. M%128==0, N%128==0, K%32==0.
// Optional batch via blockIdx.z with element strides aBat/bBat/oBat.
// Smem stage: Ahi 4K | Alo 4K | Bhi 4K | Blo 4K (32B rows, SW128 swizzle).
// ---------------------------------------------------------------------------
#define SWZB(x) ((x) ^ (((x) >> 3) & 0x70))
#define STGB 16384

__device__ __forceinline__ void ldsm4(uint32_t* r, uint32_t addr) {
    asm volatile("ldmatrix.sync.aligned.m8n8.x4.shared.b16 {%0,%1,%2,%3}, [%4];"
        : "=r"(r[0]), "=r"(r[1]), "=r"(r[2]), "=r"(r[3]) : "r"(addr));
}

__device__ __forceinline__ void mma_bf16(float* d, const uint32_t* a, const uint32_t* b) {
    asm volatile(
        "mma.sync.aligned.m16n8k16.row.col.f32.bf16.bf16.f32 "
        "{%0,%1,%2,%3}, {%4,%5,%6,%7}, {%8,%9}, {%0,%1,%2,%3};"
        : "+f"(d[0]), "+f"(d[1]), "+f"(d[2]), "+f"(d[3])
        : "r"(a[0]), "r"(a[1]), "r"(a[2]), "r"(a[3]), "r"(b[0]), "r"(b[1]));
}

__device__ __forceinline__ void split_store(char* hiP, char* loP, float4 v) {
    uint32_t h0, h1, l0, l1;
    asm("cvt.rn.bf16x2.f32 %0, %1, %2;" : "=r"(h0) : "f"(v.y), "f"(v.x));
    asm("cvt.rn.bf16x2.f32 %0, %1, %2;" : "=r"(h1) : "f"(v.w), "f"(v.z));
    float e0 = v.x - __uint_as_float(h0 << 16);
    float e1 = v.y - __uint_as_float(h0 & 0xFFFF0000u);
    float e2 = v.z - __uint_as_float(h1 << 16);
    float e3 = v.w - __uint_as_float(h1 & 0xFFFF0000u);
    asm("cvt.rn.bf16x2.f32 %0, %1, %2;" : "=r"(l0) : "f"(e1), "f"(e0));
    asm("cvt.rn.bf16x2.f32 %0, %1, %2;" : "=r"(l1) : "f"(e3), "f"(e2));
    *(uint2*)hiP = make_uint2(h0, h1);
    *(uint2*)loP = make_uint2(l0, l1);
}

__global__ __launch_bounds__(256)
void k_gemm(const float* __restrict__ A, const float* __restrict__ W,
            const float* __restrict__ bias, const float* __restrict__ res,
            float* __restrict__ O, int M, int N, int K, int lda, int ldb,
            int act, long long aBat, long long bBat, long long oBat) {
    __shared__ __align__(1024) char sm[2*STGB];
    uint32_t sb32 = (uint32_t)__cvta_generic_to_shared(sm);

    A += (size_t)blockIdx.z * aBat;
    W += (size_t)blockIdx.z * bBat;
    O += (size_t)blockIdx.z * oBat;
    if (res) res += (size_t)blockIdx.z * oBat;

    int tid = threadIdx.x;
    int lane = tid & 31, warp = tid >> 5;
    int wm = warp >> 1, wn = warp & 1;           // warp grid 4x2, warp tile 32x64
    int m0 = blockIdx.x * 128, n0 = blockIdx.y * 128;

    int gr = tid >> 2;            // row 0..63
    int j8 = (tid & 3) * 8;       // byte offset within 32B row
    const float* Ap0 = A + (size_t)(m0 + gr)*lda + (tid & 3)*4;
    const float* Ap1 = Ap0 + (size_t)64*lda;
    const float* Bp0 = W + (size_t)(n0 + gr)*ldb + (tid & 3)*4;
    const float* Bp1 = Bp0 + (size_t)64*ldb;

    int off0 = SWZB(gr*32 + j8);
    int off1 = SWZB((gr+64)*32 + j8);

    // ldmatrix addresses (stage-0 base)
    int mrow = wm*32 + (lane & 15);
    int aseg = (lane >> 4) & 1;
    uint32_t adr_a0 = sb32 + SWZB(mrow*32 + aseg*16);
    uint32_t adr_a1 = sb32 + SWZB((mrow+16)*32 + aseg*16);
    int nbase = wn*64 + (lane & 7) + ((lane >> 4) << 3);
    int bseg = (lane >> 3) & 1;
    uint32_t adr_b[4];
#pragma unroll
    for (int g = 0; g < 4; g++)
        adr_b[g] = sb32 + 8192 + SWZB((nbase + g*16)*32 + bseg*16);

    float acc[2][8][4];
#pragma unroll
    for (int i = 0; i < 2; i++)
#pragma unroll
        for (int j = 0; j < 8; j++)
#pragma unroll
            for (int v = 0; v < 4; v++) acc[i][j][v] = 0.0f;

    int r = lane >> 2, c = lane & 3;

    float4 av0, av1, bv0, bv1;
    auto gload = [&]() {
        av0 = *(const float4*)Ap0;
        av1 = *(const float4*)Ap1;
        bv0 = *(const float4*)Bp0;
        bv1 = *(const float4*)Bp1;
        Ap0 += 16; Ap1 += 16; Bp0 += 16; Bp1 += 16;
    };

    auto cstore = [&](char* st) {
        split_store(st + off0,        st + 4096  + off0, av0);
        split_store(st + off1,        st + 4096  + off1, av1);
        split_store(st + 8192 + off0, st + 12288 + off0, bv0);
        split_store(st + 8192 + off1, st + 12288 + off1, bv1);
    };

    auto comp = [&](uint32_t so) {
        uint32_t ah[2][4], al[2][4];
        ldsm4(ah[0], adr_a0 + so);
        ldsm4(ah[1], adr_a1 + so);
        ldsm4(al[0], adr_a0 + so + 4096);
        ldsm4(al[1], adr_a1 + so + 4096);
#pragma unroll
        for (int g = 0; g < 4; g++) {
            uint32_t th[4], tl[4];
            ldsm4(th, adr_b[g] + so);
            ldsm4(tl, adr_b[g] + so + 4096);
#pragma unroll
            for (int mf = 0; mf < 2; mf++) {
                mma_bf16(acc[mf][2*g],   ah[mf], th);
                mma_bf16(acc[mf][2*g],   ah[mf], tl);
                mma_bf16(acc[mf][2*g],   al[mf], th);
                mma_bf16(acc[mf][2*g+1], ah[mf], th+2);
                mma_bf16(acc[mf][2*g+1], ah[mf], tl+2);
                mma_bf16(acc[mf][2*g+1], al[mf], th+2);
            }
        }
    };

    int nk = K >> 4;   // all K multiples of 32 -> nk even
    gload();
    cstore(sm);
    __syncthreads();
    for (int i2 = 0; i2 < nk; i2 += 2) {
        gload();                       // tile i2+1
        comp(0);                       // stage 0 (tile i2)
        cstore(sm + STGB);
        __syncthreads();
        bool more = (i2 + 2 < nk);
        if (more) gload();             // tile i2+2
        comp(STGB);                    // stage 1 (tile i2+1)
        if (more) cstore(sm);
        __syncthreads();
    }

    // epilogue: c0:(r, 2c) c1:(r, 2c+1) c2:(r+8, 2c) c3:(r+8, 2c+1)
#pragma unroll
    for (int mf = 0; mf < 2; mf++) {
        int m = m0 + wm*32 + mf*16 + r;
#pragma unroll
        for (int nf = 0; nf < 8; nf++) {
            int n = n0 + wn*64 + nf*8 + c*2;
            float v0 = acc[mf][nf][0], v1 = acc[mf][nf][1];
            float v2 = acc[mf][nf][2], v3 = acc[mf][nf][3];
            if (bias) {
                float b0 = bias[n], b1 = bias[n+1];
                v0 += b0; v1 += b1; v2 += b0; v3 += b1;
            }
            if (act) {
                v0 = gelu1(v0); v1 = gelu1(v1); v2 = gelu1(v2); v3 = gelu1(v3);
            }
            if (res) {
                v0 += res[(size_t)m*N + n];
                v1 += res[(size_t)m*N + n + 1];
                v2 += res[(size_t)(m+8)*N + n];
                v3 += res[(size_t)(m+8)*N + n + 1];
            }
            O[(size_t)m*N + n]         = v0;
            O[(size_t)m*N + n + 1]     = v1;
            O[(size_t)(m+8)*N + n]     = v2;
            O[(size_t)(m+8)*N + n + 1] = v3;
        }
    }
}

// ---------------------------------------------------------------------------
// entmax (alpha = 1.000001), closed form AT THE BISECTION ROOT.
// With tau = maxv-1+eps, w = Q*eps: constraint e^A+e^B=1 gives
//   w = log1p(exp(z)),  z = Q*log1p(-|X|)  (<= 0)
// and the normalized logit at the root is sign(r) * (-z + |X|*w).
// Exact to O(Q*eps^2) ~ 5e-7 — matches the reference's frozen f32 bisection
// to its own resolution (~r*ulp(1) ~ 4e-6). Stores log(p).
// ---------------------------------------------------------------------------
__global__ void k_entmax(float* __restrict__ pT, const float* __restrict__ int_bias,
                         int l, float am1f) {
    long long i = (long long)blockIdx.x * blockDim.x + threadIdx.x;
    if (i >= (long long)BN*TN*TN) return;
    int q = (int)(i % TN);
    int k = (int)((i / TN) % TN);
    if (q <= k) return;

    float rr = pT[i]*0.125f + int_bias[l];
    float t = rr * am1f;                        // X = r*(alpha-1), |X| <= ~1e-4
    float ax = fabsf(t);
    // z = Q*log1p(-ax) = -Q*(ax + ax^2/2 + ax^3/3)
    float z = -1.0e6f * ax * fmaf(ax, fmaf(ax, 0.33333334f, 0.5f), 1.0f);
    float w = log1pf(expf(z));                  // z <= 0, safe
    float logit = -z + ax*w;
    if (t <= 0.0f) logit = -logit;
    // log p = log sigmoid(logit)
    float lp = (logit >= 0.0f) ? -log1pf(expf(-logit)) : logit - log1pf(expf(logit));
    pT[i] = lp;
}

// ---------------------------------------------------------------------------
// mask[b][q][k] += cumsum_{k<q'<=q} logp[b][k][q']   (parallel scan per column)
// ---------------------------------------------------------------------------
__global__ void k_mask(const float* __restrict__ pT, float* __restrict__ mask) {
    int col = blockIdx.x;
    int b = col >> 10, k = col & (TN-1);
    const float* pr = pT + ((size_t)b*TN + k)*TN;
    float* mcol = mask + (size_t)b*TN*TN + k;
    int tid = threadIdx.x;
    int lane = tid & 31, wid = tid >> 5;
    __shared__ float wsum[8];
    __shared__ float s_carry;
    if (tid == 0) s_carry = 0.0f;
    __syncthreads();

    for (int q0 = 0; q0 < TN; q0 += 256) {
        int q = q0 + tid;
        float v = (q > k) ? pr[q] : 0.0f;
#pragma unroll
        for (int o = 1; o < 32; o <<= 1) {
            float nv = __shfl_up_sync(0xFFFFFFFFu, v, o);
            if (lane >= o) v += nv;
        }
        if (lane == 31) wsum[wid] = v;
        __syncthreads();
        if (wid == 0) {
            float w = (lane < 8) ? wsum[lane] : 0.0f;
#pragma unroll
            for (int o = 1; o < 8; o <<= 1) {
                float nw = __shfl_up_sync(0xFFFFFFFFu, w, o);
                if (lane >= o) w += nw;
            }
            if (lane < 8) wsum[lane] = w;
        }
        __syncthreads();
        float incl = s_carry + (wid > 0 ? wsum[wid-1] : 0.0f) + v;
        if (q > k) mcol[(size_t)q*TN] += incl;
        __syncthreads();
        if (tid == 255) s_carry = incl;
        __syncthreads();
    }
}

// ---------------------------------------------------------------------------
// Attention: one block per (q, h, b).
// ---------------------------------------------------------------------------
__global__ void k_attn(const float* __restrict__ qkv, const float* __restrict__ mask,
                       float* __restrict__ y) {
    int qi = blockIdx.x, h = blockIdx.y, b = blockIdx.z;
    int tid = threadIdx.x;   // 128
    __shared__ float qs[HDN];
    __shared__ float s[TN];
    __shared__ float red[128];

    const float* base = qkv + (size_t)(b*TN)*3*CN;
    const float* qrow = base + (size_t)qi*3*CN + h*HDN;
    if (tid < HDN) qs[tid] = qrow[tid];
    __syncthreads();

    const float* mrow = mask + ((size_t)(b*TN) + qi)*TN;
    float lmax = -INFINITY;
    for (int k = tid; k <= qi; k += 128) {
        const float* krow = base + (size_t)k*3*CN + CN + h*HDN;
        float dot = 0.0f;
#pragma unroll
        for (int d = 0; d < HDN; d += 4) {
            float4 kv4 = *(const float4*)(krow + d);
            dot += qs[d]*kv4.x + qs[d+1]*kv4.y + qs[d+2]*kv4.z + qs[d+3]*kv4.w;
        }
        float sc = dot*0.125f + mrow[k];
        s[k] = sc;
        lmax = fmaxf(lmax, sc);
    }
    red[tid] = lmax; __syncthreads();
    for (int st = 64; st > 0; st >>= 1) {
        if (tid < st) red[tid] = fmaxf(red[tid], red[tid+st]);
        __syncthreads();
    }
    float m = red[0];
    __syncthreads();

    float lsum = 0.0f;
    for (int k = tid; k <= qi; k += 128) {
        float e = expf(s[k] - m);
        s[k] = e;
        lsum += e;
    }
    red[tid] = lsum; __syncthreads();
    for (int st = 64; st > 0; st >>= 1) {
        if (tid < st) red[tid] += red[tid+st];
        __syncthreads();
    }
    float inv = 1.0f / red[0];
    __syncthreads();

    int d = tid & 63, part = tid >> 6;
    float acc = 0.0f;
    for (int k = part; k <= qi; k += 2)
        acc += s[k] * base[(size_t)k*3*CN + 2*CN + h*HDN + d];
    red[tid] = acc; __syncthreads();
    if (tid < 64) {
        float tot = (red[tid] + red[tid+64]) * inv;
        y[((size_t)(b*TN) + qi)*CN + h*HDN + d] = tot;
    }
}

// ---------------------------------------------------------------------------
// Host orchestration
// ---------------------------------------------------------------------------
extern "C" void kernel_launch(void* const* d_in, const int* in_sizes, int n_in,
                              void* d_out, int out_size) {
    const float* wte    = (const float*)d_in[0];
    const float* wpe    = (const float*)d_in[1];
    const float* ln1_w  = (const float*)d_in[2];
    const float* ln1_b  = (const float*)d_in[3];
    const float* attn_w = (const float*)d_in[4];
    const float* attn_b = (const float*)d_in[5];
    const float* qint_w = (const float*)d_in[6];
    const float* kint_w = (const float*)d_in[7];
    const float* int_bias = (const float*)d_in[8];
    const float* proj_w = (const float*)d_in[9];
    const float* proj_b = (const float*)d_in[10];
    const float* ln2_w  = (const float*)d_in[11];
    const float* ln2_b  = (const float*)d_in[12];
    const float* fc_w   = (const float*)d_in[13];
    const float* fc_b   = (const float*)d_in[14];
    const float* fc2_w  = (const float*)d_in[15];
    const float* fc2_b  = (const float*)d_in[16];
    const float* lnf_w  = (const float*)d_in[17];
    const float* lnf_b  = (const float*)d_in[18];
    const int*   idx    = (const int*)d_in[19];
    float* out = (float*)d_out;

    float *px, *ph, *pqkv, *py, *pqk, *pw2, *pp, *pmask, *pfc;
    cudaGetSymbolAddress((void**)&px,    g_x);
    cudaGetSymbolAddress((void**)&ph,    g_h);
    cudaGetSymbolAddress((void**)&pqkv,  g_qkv);
    cudaGetSymbolAddress((void**)&py,    g_y);
    cudaGetSymbolAddress((void**)&pqk,   g_qk);
    cudaGetSymbolAddress((void**)&pw2,   g_w2);
    cudaGetSymbolAddress((void**)&pp,    g_p);
    cudaGetSymbolAddress((void**)&pmask, g_mask);
    cudaGetSymbolAddress((void**)&pfc,   g_fc);

    double am1d = 1.000001 - 1.0;
    float am1f = (float)am1d;

    k_embed<<<(MN*CN + 255)/256, 256>>>(wte, wpe, idx, px);
    k_zero<<<1024, 256>>>(pmask, BN*TN*TN);

    for (int l = 0; l < LN; ++l) {
        // --- attention sub-block ---
        k_ln<<<MN, 256>>>(px, ln1_w + l*CN, ln1_b + l*CN, ph);
        k_gemm<<<dim3(MN/128, 3*CN/128), 256>>>(ph, attn_w + (size_t)l*3*CN*CN,
                attn_b + l*3*CN, nullptr, pqkv, MN, 3*CN, CN, CN, CN, 0, 0, 0, 0);
        // fused qint+kint projection: [MN,128] = h @ [qint_w;kint_w]^T
        k_catw<<<(128*CN + 255)/256, 256>>>(qint_w + (size_t)l*DIN*CN,
                                            kint_w + (size_t)l*DIN*CN, pw2);
        k_gemm<<<dim3(MN/128, 1), 256>>>(ph, pw2, nullptr, nullptr, pqk,
                MN, 128, CN, CN, CN, 0, 0, 0, 0);
        // rawT[b][k][q] = kint[b,k,:] . qint[b,q,:]  (batched over b)
        k_gemm<<<dim3(TN/128, TN/128, BN), 256>>>(pqk + 64, pqk, nullptr, nullptr, pp,
                TN, TN, DIN, 128, 128, 0, (long long)TN*128, (long long)TN*128,
                (long long)TN*TN);
        k_entmax<<<(BN*TN*TN + 255)/256, 256>>>(pp, int_bias, l, am1f);
        k_mask<<<BN*TN, 256>>>(pp, pmask);
        k_attn<<<dim3(TN, HN, BN), 128>>>(pqkv, pmask, py);
        k_gemm<<<dim3(MN/128, CN/128), 256>>>(py, proj_w + (size_t)l*CN*CN,
                proj_b + l*CN, px, px, MN, CN, CN, CN, CN, 0, 0, 0, 0);
        // --- MLP sub-block (GELU fused into fc epilogue) ---
        k_ln<<<MN, 256>>>(px, ln2_w + l*CN, ln2_b + l*CN, ph);
        k_gemm<<<dim3(MN/128, CFN/128), 256>>>(ph, fc_w + (size_t)l*CFN*CN,
                fc_b + l*CFN, nullptr, pfc, MN, CFN, CN, CN, CN, 1, 0, 0, 0);
        k_gemm<<<dim3(MN/128, CN/128), 256>>>(pfc, fc2_w + (size_t)l*CN*CFN,
                fc2_b + l*CN, px, px, MN, CN, CFN, CFN, CFN, 0, 0, 0, 0);
    }

    k_ln<<<MN, 256>>>(px, lnf_w, lnf_b, ph);
    k_gemm<<<dim3(MN/128, VN/128), 256>>>(ph, wte, nullptr, nullptr, out,
            MN, VN, CN, CN, CN, 0, 0, 0, 0);
}

// round 10
// speedup vs baseline: 1.8801x; 1.8801x over previous
#include <cuda_runtime.h>
#include <math.h>
#include <stdint.h>

// ---------------------------------------------------------------------------
// Problem constants
// ---------------------------------------------------------------------------
#define BN 2
#define TN 1024
#define CN 768
#define HN 12
#define HDN 64
#define LN 4
#define DIN 64
#define VN 50304
#define CFN 3072          // 4*C
#define MN (BN*TN)        // 2048 rows

// ---------------------------------------------------------------------------
// Scratch (static device globals; allocation APIs are forbidden)
// ---------------------------------------------------------------------------
__device__ float g_x[MN*CN];
__device__ float g_h[MN*CN];
__device__ float g_qkv[MN*3*CN];
__device__ float g_y[MN*CN];
__device__ float g_qk[MN*128];      // fused [qint(64) | kint(64)] activations
__device__ float g_w2[128*CN];      // concatenated qint_w/kint_w
__device__ float g_p[BN*TN*TN];     // rawT then log-p, layout [b][k][q]
__device__ float g_mask[BN*TN*TN];  // accumulated attn_mask, layout [b][q][k]
__device__ float g_fc[MN*CFN];

// ---------------------------------------------------------------------------
// Embedding: x = wte[idx] + wpe[:T]
// ---------------------------------------------------------------------------
__global__ void k_embed(const float* __restrict__ wte, const float* __restrict__ wpe,
                        const int* __restrict__ idx, float* __restrict__ x) {
    int i = blockIdx.x * blockDim.x + threadIdx.x;
    if (i >= MN*CN) return;
    int c = i % CN;
    int bt = i / CN;
    int t = bt % TN;
    x[i] = wte[(size_t)idx[bt]*CN + c] + wpe[t*CN + c];
}

__global__ void k_zero(float* __restrict__ p, int n) {
    int i = blockIdx.x * blockDim.x + threadIdx.x;
    for (; i < n; i += gridDim.x * blockDim.x) p[i] = 0.0f;
}

// concat qint_w / kint_w into one [128, CN] weight
__global__ void k_catw(const float* __restrict__ qw, const float* __restrict__ kw,
                       float* __restrict__ dst) {
    int i = blockIdx.x * blockDim.x + threadIdx.x;
    if (i >= 128*CN) return;
    int row = i / CN, c = i % CN;
    dst[i] = (row < 64) ? qw[row*CN + c] : kw[(row-64)*CN + c];
}

// ---------------------------------------------------------------------------
// LayerNorm (block per row, C = 768 = 3*256)
// ---------------------------------------------------------------------------
__global__ void k_ln(const float* __restrict__ x, const float* __restrict__ w,
                     const float* __restrict__ b, float* __restrict__ o) {
    int row = blockIdx.x;
    const float* xr = x + (size_t)row*CN;
    float* orow = o + (size_t)row*CN;
    __shared__ float red[256];
    int t = threadIdx.x;
    float lx0 = xr[t], lx1 = xr[t+256], lx2 = xr[t+512];
    red[t] = lx0 + lx1 + lx2;
    __syncthreads();
    for (int st = 128; st > 0; st >>= 1) {
        if (t < st) red[t] += red[t+st];
        __syncthreads();
    }
    float mu = red[0] / (float)CN;
    __syncthreads();
    float d0 = lx0-mu, d1 = lx1-mu, d2 = lx2-mu;
    red[t] = d0*d0 + d1*d1 + d2*d2;
    __syncthreads();
    for (int st = 128; st > 0; st >>= 1) {
        if (t < st) red[t] += red[t+st];
        __syncthreads();
    }
    float var = red[0] / (float)CN;
    float inv = 1.0f / sqrtf(var + 1e-5f);
    orow[t]     = d0*inv*w[t]     + b[t];
    orow[t+256] = d1*inv*w[t+256] + b[t+256];
    orow[t+512] = d2*inv*w[t+512] + b[t+512];
}

// ---------------------------------------------------------------------------
// GELU helper (tanh approximation, matching reference constants)
// ---------------------------------------------------------------------------
__device__ __forceinline__ float gelu1(float v) {
    float inner = 0.7978845608028654f * (v + 0.044715f*v*v*v);
    return 0.5f*v*(1.0f + tanhf(inner));
}

// ---------------------------------------------------------------------------
// 2xBF16 tensor-core GEMM (hi/lo split, hh+hl+lh), double-buffered smem,
// ldmatrix fragment loads. Block tile 128x64, 8 warps (4Mx2N), warp 32x32.
// O[m,n] = sum_k A[m,k]*W[n,k] (+bias[n]) (+res[m,n]) (optional gelu)
// A:[M,K] row stride lda, W:[N,K] row stride ldb. M%128==0, N%64==0, K%32==0.
// Optional batch via blockIdx.z (element strides aBat/bBat/oBat).
// ---------------------------------------------------------------------------
#define SWZB(x) ((x) ^ (((x) >> 3) & 0x70))
#define STGB 12288     // bytes per stage: Ahi 4096 | Alo 4096 | Bhi 2048 | Blo 2048

__device__ __forceinline__ void ldsm4(uint32_t* r, uint32_t addr) {
    asm volatile("ldmatrix.sync.aligned.m8n8.x4.shared.b16 {%0,%1,%2,%3}, [%4];"
        : "=r"(r[0]), "=r"(r[1]), "=r"(r[2]), "=r"(r[3]) : "r"(addr));
}

__device__ __forceinline__ void mma_bf16(float* d, const uint32_t* a, const uint32_t* b) {
    asm volatile(
        "mma.sync.aligned.m16n8k16.row.col.f32.bf16.bf16.f32 "
        "{%0,%1,%2,%3}, {%4,%5,%6,%7}, {%8,%9}, {%0,%1,%2,%3};"
        : "+f"(d[0]), "+f"(d[1]), "+f"(d[2]), "+f"(d[3])
        : "r"(a[0]), "r"(a[1]), "r"(a[2]), "r"(a[3]), "r"(b[0]), "r"(b[1]));
}

__device__ __forceinline__ void split_store(char* hiP, char* loP, float4 v) {
    uint32_t h0, h1, l0, l1;
    asm("cvt.rn.bf16x2.f32 %0, %1, %2;" : "=r"(h0) : "f"(v.y), "f"(v.x));
    asm("cvt.rn.bf16x2.f32 %0, %1, %2;" : "=r"(h1) : "f"(v.w), "f"(v.z));
    float e0 = v.x - __uint_as_float(h0 << 16);
    float e1 = v.y - __uint_as_float(h0 & 0xFFFF0000u);
    float e2 = v.z - __uint_as_float(h1 << 16);
    float e3 = v.w - __uint_as_float(h1 & 0xFFFF0000u);
    asm("cvt.rn.bf16x2.f32 %0, %1, %2;" : "=r"(l0) : "f"(e1), "f"(e0));
    asm("cvt.rn.bf16x2.f32 %0, %1, %2;" : "=r"(l1) : "f"(e3), "f"(e2));
    *(uint2*)hiP = make_uint2(h0, h1);
    *(uint2*)loP = make_uint2(l0, l1);
}

__global__ __launch_bounds__(256, 2)
void k_gemm(const float* __restrict__ A, const float* __restrict__ W,
            const float* __restrict__ bias, const float* __restrict__ res,
            float* __restrict__ O, int M, int N, int K, int lda, int ldb,
            int act, long long aBat, long long bBat, long long oBat) {
    __shared__ __align__(1024) char sm[2*STGB];
    uint32_t sb32 = (uint32_t)__cvta_generic_to_shared(sm);

    A += (size_t)blockIdx.z * aBat;
    W += (size_t)blockIdx.z * bBat;
    O += (size_t)blockIdx.z * oBat;
    if (res) res += (size_t)blockIdx.z * oBat;

    int tid = threadIdx.x;
    int lane = tid & 31, warp = tid >> 5;
    int wm = warp >> 1, wn = warp & 1;           // warp grid 4x2
    int m0 = blockIdx.x * 128, n0 = blockIdx.y * 64;

    int gr = tid >> 2;            // row 0..63
    int j8 = (tid & 3) * 8;       // byte offset within 32B row
    const float* Ap0 = A + (size_t)(m0 + gr)*lda + (tid & 3)*4;
    const float* Ap1 = Ap0 + (size_t)64*lda;
    const float* Bp  = W + (size_t)(n0 + gr)*ldb + (tid & 3)*4;

    int offA0 = SWZB(gr*32 + j8);
    int offA1 = SWZB((gr+64)*32 + j8);

    int mrow = wm*32 + (lane & 15);
    int aseg = (lane >> 4) & 1;
    uint32_t adr_a0 = sb32 + SWZB(mrow*32 + aseg*16);
    uint32_t adr_a1 = sb32 + SWZB((mrow+16)*32 + aseg*16);
    int nrow = wn*32 + (lane & 7) + ((lane >> 4) << 3);
    int bseg = (lane >> 3) & 1;
    uint32_t adr_b0 = sb32 + 8192 + SWZB(nrow*32 + bseg*16);
    uint32_t adr_b1 = sb32 + 8192 + SWZB((nrow+16)*32 + bseg*16);

    float acc[2][4][4];
#pragma unroll
    for (int i = 0; i < 2; i++)
#pragma unroll
        for (int j = 0; j < 4; j++)
#pragma unroll
            for (int v = 0; v < 4; v++) acc[i][j][v] = 0.0f;

    int r = lane >> 2, c = lane & 3;

    float4 av0, av1, bv;
    auto gload = [&]() {
        av0 = *(const float4*)Ap0;
        av1 = *(const float4*)Ap1;
        bv  = *(const float4*)Bp;
        Ap0 += 16; Ap1 += 16; Bp += 16;
    };

    auto cstore = [&](char* st) {
        split_store(st + offA0,        st + 4096 + offA0, av0);
        split_store(st + offA1,        st + 4096 + offA1, av1);
        split_store(st + 8192 + offA0, st + 10240 + offA0, bv);
    };

    auto comp = [&](uint32_t so) {
        uint32_t ah[2][4], al[2][4], bh[4][2], bl[4][2], t[4];
        ldsm4(ah[0], adr_a0 + so);
        ldsm4(ah[1], adr_a1 + so);
        ldsm4(al[0], adr_a0 + so + 4096);
        ldsm4(al[1], adr_a1 + so + 4096);
        ldsm4(t, adr_b0 + so);
        bh[0][0]=t[0]; bh[0][1]=t[1]; bh[1][0]=t[2]; bh[1][1]=t[3];
        ldsm4(t, adr_b1 + so);
        bh[2][0]=t[0]; bh[2][1]=t[1]; bh[3][0]=t[2]; bh[3][1]=t[3];
        ldsm4(t, adr_b0 + so + 2048);
        bl[0][0]=t[0]; bl[0][1]=t[1]; bl[1][0]=t[2]; bl[1][1]=t[3];
        ldsm4(t, adr_b1 + so + 2048);
        bl[2][0]=t[0]; bl[2][1]=t[1]; bl[3][0]=t[2]; bl[3][1]=t[3];
#pragma unroll
        for (int mf = 0; mf < 2; mf++)
#pragma unroll
            for (int nf = 0; nf < 4; nf++) {
                mma_bf16(acc[mf][nf], ah[mf], bh[nf]);
                mma_bf16(acc[mf][nf], ah[mf], bl[nf]);
                mma_bf16(acc[mf][nf], al[mf], bh[nf]);
            }
    };

    int nk = K >> 4;   // all K multiples of 32 -> nk even
    gload();
    cstore(sm);
    __syncthreads();
    for (int i2 = 0; i2 < nk; i2 += 2) {
        gload();                       // tile i2+1
        comp(0);                       // stage 0 (tile i2)
        cstore(sm + STGB);
        __syncthreads();
        bool more = (i2 + 2 < nk);
        if (more) gload();             // tile i2+2
        comp(STGB);                    // stage 1 (tile i2+1)
        if (more) cstore(sm);
        __syncthreads();
    }

#pragma unroll
    for (int mf = 0; mf < 2; mf++) {
        int m = m0 + wm*32 + mf*16 + r;
#pragma unroll
        for (int nf = 0; nf < 4; nf++) {
            int n = n0 + wn*32 + nf*8 + c*2;
            float v0 = acc[mf][nf][0], v1 = acc[mf][nf][1];
            float v2 = acc[mf][nf][2], v3 = acc[mf][nf][3];
            if (bias) {
                float b0 = bias[n], b1 = bias[n+1];
                v0 += b0; v1 += b1; v2 += b0; v3 += b1;
            }
            if (act) {
                v0 = gelu1(v0); v1 = gelu1(v1); v2 = gelu1(v2); v3 = gelu1(v3);
            }
            if (res) {
                v0 += res[(size_t)m*N + n];
                v1 += res[(size_t)m*N + n + 1];
                v2 += res[(size_t)(m+8)*N + n];
                v3 += res[(size_t)(m+8)*N + n + 1];
            }
            O[(size_t)m*N + n]         = v0;
            O[(size_t)m*N + n + 1]     = v1;
            O[(size_t)(m+8)*N + n]     = v2;
            O[(size_t)(m+8)*N + n + 1] = v3;
        }
    }
}

// ---------------------------------------------------------------------------
// entmax (alpha=1.000001), f32-FAITHFUL bisection (replicates the reference's
// f32 base quantization: clip(Xs - tau) rounded to ulp(1)=6e-8, which is
// amplified 1e6x in the logit — a smooth closed form CANNOT match this).
// Freezes when tau_lo + dm == tau_lo (~5 iters). Emits log p directly.
// b^1e6 handled in log space: u+c with exact FMA residual split.
// ---------------------------------------------------------------------------
__device__ __forceinline__ float lg1e6(float b, float& z) {
    float t = b - 1.0f;                    // exact near 1
    float u = 1.0e6f * t;
    float e = fmaf(1.0e6f, t, -u);         // exact product residual
    float c = fmaf(u*t, fmaf(t, fmaf(-0.25f, t, 0.33333333333333333f), -0.5f), e);
    z = u + c;                             // 1e6*log(b)
    return expf(u) * (1.0f + c*(1.0f + 0.5f*c));   // b^1e6 (same form as proven rounds)
}

__global__ void k_entmax(float* __restrict__ pT, const float* __restrict__ int_bias,
                         int l, float am1f, float halfpow) {
    long long i = (long long)blockIdx.x * blockDim.x + threadIdx.x;
    if (i >= (long long)BN*TN*TN) return;
    int q = (int)(i % TN);
    int k = (int)((i / TN) % TN);
    if (q <= k) return;

    float r   = pT[i]*0.125f + int_bias[l];
    float Xs0 = r * am1f;
    float maxv = fmaxf(Xs0, 0.0f);
    float tau_lo = maxv - 1.0f;
    float tau_hi = maxv - halfpow;
    float dm = tau_hi - tau_lo;
    float zt;
    float f_lo = (lg1e6(fmaxf(Xs0 - tau_lo, 0.0f), zt)
                + lg1e6(fmaxf(-tau_lo, 0.0f), zt)) - 1.0f;

    float z0 = 0.0f, z1 = 0.0f;
#pragma unroll 1
    for (int it = 0; it < 50; ++it) {
        dm *= 0.5f;
        float tm = tau_lo + dm;
        float p0 = lg1e6(fmaxf(Xs0 - tm, 0.0f), z0);
        float p1 = lg1e6(fmaxf(-tm, 0.0f), z1);
        float fm = (p0 + p1) - 1.0f;
        bool take = (fm * f_lo >= 0.0f);
        if (tm == tau_lo) break;           // frozen: all later iters identical
        if (take) tau_lo = tm;
    }
    // log( p0/(p0+p1) ) = -log1p(e^(z1-z0)), stable both sides
    float d = z1 - z0;
    float lp = (d <= 0.0f) ? -log1pf(expf(d)) : -(d + log1pf(expf(-d)));
    pT[i] = lp;
}

// ---------------------------------------------------------------------------
// mask[b][q][k] += cumsum_{k<q'<=q} logp[b][k][q']   (parallel scan per column)
// ---------------------------------------------------------------------------
__global__ void k_mask(const float* __restrict__ pT, float* __restrict__ mask) {
    int col = blockIdx.x;
    int b = col >> 10, k = col & (TN-1);
    const float* pr = pT + ((size_t)b*TN + k)*TN;
    float* mcol = mask + (size_t)b*TN*TN + k;
    int tid = threadIdx.x;
    int lane = tid & 31, wid = tid >> 5;
    __shared__ float wsum[8];
    __shared__ float s_carry;
    if (tid == 0) s_carry = 0.0f;
    __syncthreads();

    for (int q0 = 0; q0 < TN; q0 += 256) {
        int q = q0 + tid;
        float v = (q > k) ? pr[q] : 0.0f;
#pragma unroll
        for (int o = 1; o < 32; o <<= 1) {
            float nv = __shfl_up_sync(0xFFFFFFFFu, v, o);
            if (lane >= o) v += nv;
        }
        if (lane == 31) wsum[wid] = v;
        __syncthreads();
        if (wid == 0) {
            float w = (lane < 8) ? wsum[lane] : 0.0f;
#pragma unroll
            for (int o = 1; o < 8; o <<= 1) {
                float nw = __shfl_up_sync(0xFFFFFFFFu, w, o);
                if (lane >= o) w += nw;
            }
            if (lane < 8) wsum[lane] = w;
        }
        __syncthreads();
        float incl = s_carry + (wid > 0 ? wsum[wid-1] : 0.0f) + v;
        if (q > k) mcol[(size_t)q*TN] += incl;
        __syncthreads();
        if (tid == 255) s_carry = incl;
        __syncthreads();
    }
}

// ---------------------------------------------------------------------------
// Tiled online-softmax attention. Grid (T/16, H, B), 256 threads (8 warps).
// 16 q-rows per block (2 per warp), K/V staged in smem tiles of 64.
// K rows padded to 65 floats -> lane-indexed dot reads conflict-free.
// V read as float2 (lane owns d=2*lane, 2*lane+1). p broadcast via shfl.
// ---------------------------------------------------------------------------
#define TQ 16
#define TK 64

__device__ __forceinline__ float wred_max(float v) {
#pragma unroll
    for (int o = 16; o > 0; o >>= 1) v = fmaxf(v, __shfl_xor_sync(0xFFFFFFFFu, v, o));
    return v;
}
__device__ __forceinline__ float wred_sum(float v) {
#pragma unroll
    for (int o = 16; o > 0; o >>= 1) v += __shfl_xor_sync(0xFFFFFFFFu, v, o);
    return v;
}

__global__ __launch_bounds__(256)
void k_attn(const float* __restrict__ qkv, const float* __restrict__ mask,
            float* __restrict__ y) {
    int q0 = blockIdx.x * TQ, h = blockIdx.y, b = blockIdx.z;
    int tid = threadIdx.x, lane = tid & 31, w = tid >> 5;
    __shared__ float qs[TQ][HDN];
    __shared__ float kt[TK][65];
    __shared__ float vt[TK][HDN];

    const float* base = qkv + (size_t)(b*TN)*3*CN;

    {   // load q tile: 16 rows x 16 float4
        int row = tid >> 4, f4 = tid & 15;
        float4 v = *(const float4*)(base + (size_t)(q0+row)*3*CN + h*HDN + f4*4);
        *(float4*)&qs[row][f4*4] = v;
    }

    int qa = q0 + w*2;                    // warp's rows: qa, qa+1
    const float* mr0 = mask + ((size_t)(b*TN) + qa)*TN;
    const float* mr1 = mr0 + TN;
    float m0 = -INFINITY, m1 = -INFINITY, l0 = 0.0f, l1 = 0.0f;
    float2 a0 = make_float2(0.f, 0.f), a1 = make_float2(0.f, 0.f);

    for (int k0 = 0; k0 < q0 + TQ; k0 += TK) {
        __syncthreads();                  // covers q-load on iter 0, tile reuse after
        {   // load K,V tile: 64 rows, 4 threads/row, 4 float4 each
            int row = tid >> 2;
            const float* kr = base + (size_t)(k0+row)*3*CN + CN + h*HDN;
            const float* vr = kr + CN;
#pragma unroll
            for (int j = 0; j < 4; j++) {
                int f4 = (tid & 3) + 4*j;
                float4 kv = *(const float4*)(kr + f4*4);
                kt[row][f4*4+0] = kv.x; kt[row][f4*4+1] = kv.y;
                kt[row][f4*4+2] = kv.z; kt[row][f4*4+3] = kv.w;
                *(float4*)&vt[row][f4*4] = *(const float4*)(vr + f4*4);
            }
        }
        __syncthreads();

        int k1 = k0 + lane, k2 = k0 + lane + 32;
#pragma unroll
        for (int qq = 0; qq < 2; qq++) {
            int qg = qa + qq;
            const float* mr = qq ? mr1 : mr0;
            float mcur = qq ? m1 : m0;
            float lcur = qq ? l1 : l0;
            float2 acur = qq ? a1 : a0;
            const float* qrow = qs[w*2 + qq];

            float d1 = 0.0f, d2 = 0.0f;
#pragma unroll
            for (int dd = 0; dd < HDN; dd++) {
                float qv = qrow[dd];
                d1 = fmaf(qv, kt[lane][dd],    d1);
                d2 = fmaf(qv, kt[lane+32][dd], d2);
            }
            float s1 = (k1 <= qg) ? fmaf(d1, 0.125f, mr[k1]) : -INFINITY;
            float s2 = (k2 <= qg) ? fmaf(d2, 0.125f, mr[k2]) : -INFINITY;

            float tmax = wred_max(fmaxf(s1, s2));
            float mnew = fmaxf(mcur, tmax);
            float sc = expf(mcur - mnew);
            float p1 = expf(s1 - mnew);
            float p2 = expf(s2 - mnew);
            float ts = wred_sum(p1 + p2);
            lcur = lcur*sc + ts;
            acur.x *= sc; acur.y *= sc;
#pragma unroll
            for (int kk = 0; kk < 32; kk++) {
                float pv = __shfl_sync(0xFFFFFFFFu, p1, kk);
                float2 vv = *(const float2*)&vt[kk][lane*2];
                acur.x = fmaf(pv, vv.x, acur.x);
                acur.y = fmaf(pv, vv.y, acur.y);
            }
#pragma unroll
            for (int kk = 0; kk < 32; kk++) {
                float pv = __shfl_sync(0xFFFFFFFFu, p2, kk);
                float2 vv = *(const float2*)&vt[kk+32][lane*2];
                acur.x = fmaf(pv, vv.x, acur.x);
                acur.y = fmaf(pv, vv.y, acur.y);
            }
            if (qq) { m1 = mnew; l1 = lcur; a1 = acur; }
            else    { m0 = mnew; l0 = lcur; a0 = acur; }
        }
    }

    float inv0 = 1.0f / l0, inv1 = 1.0f / l1;
    float* y0 = y + ((size_t)(b*TN) + qa)*CN + h*HDN + lane*2;
    *(float2*)y0        = make_float2(a0.x*inv0, a0.y*inv0);
    *(float2*)(y0 + CN) = make_float2(a1.x*inv1, a1.y*inv1);
}

// ---------------------------------------------------------------------------
// Host orchestration
// ---------------------------------------------------------------------------
extern "C" void kernel_launch(void* const* d_in, const int* in_sizes, int n_in,
                              void* d_out, int out_size) {
    const float* wte    = (const float*)d_in[0];
    const float* wpe    = (const float*)d_in[1];
    const float* ln1_w  = (const float*)d_in[2];
    const float* ln1_b  = (const float*)d_in[3];
    const float* attn_w = (const float*)d_in[4];
    const float* attn_b = (const float*)d_in[5];
    const float* qint_w = (const float*)d_in[6];
    const float* kint_w = (const float*)d_in[7];
    const float* int_bias = (const float*)d_in[8];
    const float* proj_w = (const float*)d_in[9];
    const float* proj_b = (const float*)d_in[10];
    const float* ln2_w  = (const float*)d_in[11];
    const float* ln2_b  = (const float*)d_in[12];
    const float* fc_w   = (const float*)d_in[13];
    const float* fc_b   = (const float*)d_in[14];
    const float* fc2_w  = (const float*)d_in[15];
    const float* fc2_b  = (const float*)d_in[16];
    const float* lnf_w  = (const float*)d_in[17];
    const float* lnf_b  = (const float*)d_in[18];
    const int*   idx    = (const int*)d_in[19];
    float* out = (float*)d_out;

    float *px, *ph, *pqkv, *py, *pqk, *pw2, *pp, *pmask, *pfc;
    cudaGetSymbolAddress((void**)&px,    g_x);
    cudaGetSymbolAddress((void**)&ph,    g_h);
    cudaGetSymbolAddress((void**)&pqkv,  g_qkv);
    cudaGetSymbolAddress((void**)&py,    g_y);
    cudaGetSymbolAddress((void**)&pqk,   g_qk);
    cudaGetSymbolAddress((void**)&pw2,   g_w2);
    cudaGetSymbolAddress((void**)&pp,    g_p);
    cudaGetSymbolAddress((void**)&pmask, g_mask);
    cudaGetSymbolAddress((void**)&pfc,   g_fc);

    double am1d = 1.000001 - 1.0;
    float am1f = (float)am1d;
    float halfpow = (float)pow(0.5, am1d);

    k_embed<<<(MN*CN + 255)/256, 256>>>(wte, wpe, idx, px);
    k_zero<<<1024, 256>>>(pmask, BN*TN*TN);

    for (int l = 0; l < LN; ++l) {
        // --- attention sub-block ---
        k_ln<<<MN, 256>>>(px, ln1_w + l*CN, ln1_b + l*CN, ph);
        k_gemm<<<dim3(MN/128, 3*CN/64), 256>>>(ph, attn_w + (size_t)l*3*CN*CN,
                attn_b + l*3*CN, nullptr, pqkv, MN, 3*CN, CN, CN, CN, 0, 0, 0, 0);
        // fused qint+kint projection: [MN,128] = h @ [qint_w;kint_w]^T
        k_catw<<<(128*CN + 255)/256, 256>>>(qint_w + (size_t)l*DIN*CN,
                                            kint_w + (size_t)l*DIN*CN, pw2);
        k_gemm<<<dim3(MN/128, 2), 256>>>(ph, pw2, nullptr, nullptr, pqk,
                MN, 128, CN, CN, CN, 0, 0, 0, 0);
        // rawT[b][k][q] = kint[b,k,:] . qint[b,q,:]  (batched over b)
        k_gemm<<<dim3(TN/128, TN/64, BN), 256>>>(pqk + 64, pqk, nullptr, nullptr, pp,
                TN, TN, DIN, 128, 128, 0, (long long)TN*128, (long long)TN*128,
                (long long)TN*TN);
        k_entmax<<<(BN*TN*TN + 255)/256, 256>>>(pp, int_bias, l, am1f, halfpow);
        k_mask<<<BN*TN, 256>>>(pp, pmask);
        k_attn<<<dim3(TN/TQ, HN, BN), 256>>>(pqkv, pmask, py);
        k_gemm<<<dim3(MN/128, CN/64), 256>>>(py, proj_w + (size_t)l*CN*CN,
                proj_b + l*CN, px, px, MN, CN, CN, CN, CN, 0, 0, 0, 0);
        // --- MLP sub-block (GELU fused into fc epilogue) ---
        k_ln<<<MN, 256>>>(px, ln2_w + l*CN, ln2_b + l*CN, ph);
        k_gemm<<<dim3(MN/128, CFN/64), 256>>>(ph, fc_w + (size_t)l*CFN*CN,
                fc_b + l*CFN, nullptr, pfc, MN, CFN, CN, CN, CN, 1, 0, 0, 0);
        k_gemm<<<dim3(MN/128, CN/64), 256>>>(pfc, fc2_w + (size_t)l*CN*CFN,
                fc2_b + l*CN, px, px, MN, CN, CFN, CFN, CFN, 0, 0, 0, 0);
    }

    k_ln<<<MN, 256>>>(px, lnf_w, lnf_b, ph);
    k_gemm<<<dim3(MN/128, VN/64), 256>>>(ph, wte, nullptr, nullptr, out,
            MN, VN, CN, CN, CN, 0, 0, 0, 0);
}